// round 6
// baseline (speedup 1.0000x reference)
#include <cuda_runtime.h>
#include <cstdint>
#include <cstddef>

#define NMAX 50000
#define EMAX 1600000
#define NEG_BIG (-1.0e30f)

__device__ float g_Q[(size_t)NMAX * 128];    // Q scratch, reused as TMP
__device__ float g_qk[(size_t)NMAX * 512];   // [n][h*128+j]
__device__ float g_agg[(size_t)NMAX * 512];  // [n][h*128+j] normalized aggregate
__device__ int   g_rs[NMAX + 1];

typedef unsigned long long ull;
__device__ __forceinline__ ull f2_pack(float x, float y) {
    ull r; asm("mov.b64 %0, {%1,%2};" : "=l"(r) : "f"(x), "f"(y)); return r;
}
__device__ __forceinline__ void f2_fma(ull& a, ull b, ull c) {
    asm("fma.rn.f32x2 %0, %1, %2, %0;" : "+l"(a) : "l"(b), "l"(c));
}
__device__ __forceinline__ float f2_sum(ull v) {
    float x, y; asm("mov.b64 {%0,%1}, %2;" : "=f"(x), "=f"(y) : "l"(v)); return x + y;
}

// ---- segment bounds from sorted center_id ----
__global__ void k_init_rs(int N, int E) {
    int t = blockIdx.x * blockDim.x + threadIdx.x;
    if (t <= N) g_rs[t] = E;
}
__global__ void k_bounds(const int* __restrict__ center, int E) {
    int e = blockIdx.x * blockDim.x + threadIdx.x;
    if (e >= E) return;
    int c = center[e];
    int p = (e == 0) ? -1 : center[e - 1];
    for (int n = p + 1; n <= c; n++) g_rs[n] = e;
}

#define RB 4  // rows per iteration in dense kernels

// ---- Y[n,i] = sum_k X[n,k]*W[i*128+k] ----
__global__ __launch_bounds__(512, 2) void k_dense128(const float* __restrict__ X,
                                                     const float* __restrict__ W,
                                                     float* __restrict__ Y, int N) {
    __shared__ alignas(16) float x_s[RB][128];
    __shared__ float part_s[RB][4][128];
    int t = threadIdx.x, i = t & 127, kq = t >> 7;
    ull w2[16];
    const float* wp = W + (size_t)i * 128 + kq * 32;
#pragma unroll
    for (int c = 0; c < 16; c++) { float2 v = *(const float2*)(wp + 2 * c); w2[c] = f2_pack(v.x, v.y); }
    for (int base = blockIdx.x * RB; base < N; base += gridDim.x * RB) {
        if (t < RB * 32) {
            int r = t >> 5, c4 = t & 31, n = base + r;
            float4 v = (n < N) ? *(const float4*)(X + (size_t)n * 128 + c4 * 4)
                               : make_float4(0.f, 0.f, 0.f, 0.f);
            *(float4*)(&x_s[r][c4 * 4]) = v;
        }
        __syncthreads();
        ull a[RB];
#pragma unroll
        for (int r = 0; r < RB; r++) a[r] = 0ull;
#pragma unroll
        for (int c = 0; c < 16; c++) {
#pragma unroll
            for (int r = 0; r < RB; r++) {
                ull u = *(const ull*)(&x_s[r][kq * 32 + 2 * c]);  // LDS.64, no packs
                f2_fma(a[r], w2[c], u);
            }
        }
#pragma unroll
        for (int r = 0; r < RB; r++) part_s[r][kq][i] = f2_sum(a[r]);
        __syncthreads();
        {
            int r = t >> 7, ii = t & 127, n = base + r;
            if (n < N)
                Y[(size_t)n * 128 + ii] = part_s[r][0][ii] + part_s[r][1][ii] +
                                          part_s[r][2][ii] + part_s[r][3][ii];
        }
        __syncthreads();
    }
}

// ---- qk[n,h*128+j] = SC * sum_d Q[n,h*32+d]*W_K[(h*32+d)*128+j] ----
__global__ __launch_bounds__(512, 2) void k_qk(const float* __restrict__ Q,
                                               const float* __restrict__ WK, int N) {
    __shared__ alignas(16) float q_s[RB][128];
    int t = threadIdx.x, h = t >> 7, j = t & 127;
    ull w2[16];
#pragma unroll
    for (int c = 0; c < 16; c++)
        w2[c] = f2_pack(WK[(size_t)(h * 32 + 2 * c) * 128 + j],
                        WK[(size_t)(h * 32 + 2 * c + 1) * 128 + j]);
    const float SC = 0.17677669529663687f;  // 1/sqrt(32)
    for (int base = blockIdx.x * RB; base < N; base += gridDim.x * RB) {
        if (t < RB * 32) {
            int r = t >> 5, c4 = t & 31, n = base + r;
            float4 v = (n < N) ? *(const float4*)(Q + (size_t)n * 128 + c4 * 4)
                               : make_float4(0.f, 0.f, 0.f, 0.f);
            *(float4*)(&q_s[r][c4 * 4]) = v;
        }
        __syncthreads();
        ull a[RB];
#pragma unroll
        for (int r = 0; r < RB; r++) a[r] = 0ull;
#pragma unroll
        for (int c = 0; c < 16; c++) {
#pragma unroll
            for (int r = 0; r < RB; r++) {
                ull u = *(const ull*)(&q_s[r][h * 32 + 2 * c]);
                f2_fma(a[r], w2[c], u);
            }
        }
#pragma unroll
        for (int r = 0; r < RB; r++)
            if (base + r < N) g_qk[(size_t)(base + r) * 512 + t] = f2_sum(a[r]) * SC;
        __syncthreads();
    }
}

// ---- TMP[n,i] = sum_j W_V[i*128+j] * AG[n,(i>>5)*128+j] ----
__global__ __launch_bounds__(512, 2) void k_vagg(const float* __restrict__ WV,
                                                 float* __restrict__ TMP, int N) {
    __shared__ alignas(16) float ag_s[RB][512];
    __shared__ float part_s[RB][4][128];
    int t = threadIdx.x, i = t & 127, kq = t >> 7, h = i >> 5;
    ull w2[16];
    const float* wp = WV + (size_t)i * 128 + kq * 32;
#pragma unroll
    for (int c = 0; c < 16; c++) { float2 v = *(const float2*)(wp + 2 * c); w2[c] = f2_pack(v.x, v.y); }
    for (int base = blockIdx.x * RB; base < N; base += gridDim.x * RB) {
        {
            int r = t >> 7, c4 = t & 127, n = base + r;
            float4 v = (n < N) ? *(const float4*)(g_agg + (size_t)n * 512 + c4 * 4)
                               : make_float4(0.f, 0.f, 0.f, 0.f);
            *(float4*)(&ag_s[r][c4 * 4]) = v;
        }
        __syncthreads();
        ull a[RB];
#pragma unroll
        for (int r = 0; r < RB; r++) a[r] = 0ull;
#pragma unroll
        for (int c = 0; c < 16; c++) {
#pragma unroll
            for (int r = 0; r < RB; r++) {
                ull u = *(const ull*)(&ag_s[r][h * 128 + kq * 32 + 2 * c]);
                f2_fma(a[r], w2[c], u);
            }
        }
#pragma unroll
        for (int r = 0; r < RB; r++) part_s[r][kq][i] = f2_sum(a[r]);
        __syncthreads();
        {
            int r = t >> 7, ii = t & 127, n = base + r;
            if (n < N)
                TMP[(size_t)n * 128 + ii] = part_s[r][0][ii] + part_s[r][1][ii] +
                                            part_s[r][2][ii] + part_s[r][3][ii];
        }
        __syncthreads();
    }
}

// ---- per-node single pass over h_E: register-resident online softmax + agg ----
// 256 threads = 8 warps; chunk = 32 edges, warp owns 4; lane owns 4 columns (4l..4l+3).
__global__ __launch_bounds__(256) void k_node(const float* __restrict__ hE, int N) {
    __shared__ float lgT[4][32];
    __shared__ float pT[4][32];
    __shared__ float m_s[4], s_s[4], sc_s[4];
    __shared__ float red_s[8][512];
    int t = threadIdx.x, w = t >> 5, l = t & 31;
    int n = blockIdx.x;
    int beg = g_rs[n], end = g_rs[n + 1];

    float qk[4][4];
    {
        const float4* qp = (const float4*)(g_qk + (size_t)n * 512);
#pragma unroll
        for (int h = 0; h < 4; h++) {
            float4 v = qp[h * 32 + l];
            qk[h][0] = v.x; qk[h][1] = v.y; qk[h][2] = v.z; qk[h][3] = v.w;
        }
    }
    if (t < 4) { m_s[t] = NEG_BIG; s_s[t] = 0.f; }
    float acc[4][4];
#pragma unroll
    for (int h = 0; h < 4; h++)
#pragma unroll
        for (int c = 0; c < 4; c++) acc[h][c] = 0.f;
    __syncthreads();

    for (int cs = beg; cs < end; cs += 32) {
        int e0 = cs + w * 4;
        float x[4][4];
#pragma unroll
        for (int i = 0; i < 4; i++) {
            int e = e0 + i;
            if (e < end) {
                float4 v = *(const float4*)(hE + (size_t)e * 128 + 4 * l);
                x[i][0] = v.x; x[i][1] = v.y; x[i][2] = v.z; x[i][3] = v.w;
            } else {
                x[i][0] = 0.f; x[i][1] = 0.f; x[i][2] = 0.f; x[i][3] = 0.f;
            }
        }
        // logits: per-lane partials then 16-way warp butterfly
        float part[4][4];
#pragma unroll
        for (int i = 0; i < 4; i++)
#pragma unroll
            for (int h = 0; h < 4; h++)
                part[i][h] = qk[h][0] * x[i][0] + qk[h][1] * x[i][1] +
                             qk[h][2] * x[i][2] + qk[h][3] * x[i][3];
#pragma unroll
        for (int off = 16; off; off >>= 1)
#pragma unroll
            for (int i = 0; i < 4; i++)
#pragma unroll
                for (int h = 0; h < 4; h++)
                    part[i][h] += __shfl_xor_sync(0xffffffffu, part[i][h], off);
        if (l == 0) {
#pragma unroll
            for (int i = 0; i < 4; i++)
#pragma unroll
                for (int h = 0; h < 4; h++)
                    lgT[h][w * 4 + i] = (e0 + i < end) ? part[i][h] : NEG_BIG;
        }
        __syncthreads();
        if (w < 4) {  // per-head running max + rescale factor
            float v = lgT[w][l];
#pragma unroll
            for (int off = 16; off; off >>= 1)
                v = fmaxf(v, __shfl_xor_sync(0xffffffffu, v, off));
            if (l == 0) {
                float old = m_s[w], nm = fmaxf(old, v);
                sc_s[w] = __expf(old - nm);
                m_s[w] = nm;
            }
        }
        __syncthreads();
        if (w < 4) {  // p + running sum
            float p = __expf(lgT[w][l] - m_s[w]);
            pT[w][l] = p;
            float sv = p;
#pragma unroll
            for (int off = 16; off; off >>= 1)
                sv += __shfl_xor_sync(0xffffffffu, sv, off);
            if (l == 0) s_s[w] = s_s[w] * sc_s[w] + sv;
        }
        __syncthreads();
        // accumulate (all warps): rescale then FMA with this chunk's p
        {
            float s0 = sc_s[0], s1 = sc_s[1], s2 = sc_s[2], s3 = sc_s[3];
#pragma unroll
            for (int c = 0; c < 4; c++) {
                acc[0][c] *= s0; acc[1][c] *= s1; acc[2][c] *= s2; acc[3][c] *= s3;
            }
#pragma unroll
            for (int i = 0; i < 4; i++) {
                float p0 = pT[0][w * 4 + i], p1 = pT[1][w * 4 + i];
                float p2 = pT[2][w * 4 + i], p3 = pT[3][w * 4 + i];
#pragma unroll
                for (int c = 0; c < 4; c++) {
                    acc[0][c] = fmaf(p0, x[i][c], acc[0][c]);
                    acc[1][c] = fmaf(p1, x[i][c], acc[1][c]);
                    acc[2][c] = fmaf(p2, x[i][c], acc[2][c]);
                    acc[3][c] = fmaf(p3, x[i][c], acc[3][c]);
                }
            }
        }
        __syncthreads();
    }
    // cross-warp reduce + normalize
#pragma unroll
    for (int h = 0; h < 4; h++)
        *(float4*)(&red_s[w][h * 128 + 4 * l]) =
            make_float4(acc[h][0], acc[h][1], acc[h][2], acc[h][3]);
    __syncthreads();
    for (int o = t; o < 512; o += 256) {
        float s = 0.f;
#pragma unroll
        for (int ww = 0; ww < 8; ww++) s += red_s[ww][o];
        int h = o >> 7;
        float inv = (end > beg) ? (1.0f / s_s[h]) : 0.f;
        g_agg[(size_t)n * 512 + o] = s * inv;
    }
}

extern "C" void kernel_launch(void* const* d_in, const int* in_sizes, int n_in,
                              void* d_out, int out_size) {
    const float* hV = (const float*)d_in[0];
    const float* hE = (const float*)d_in[1];
    const int* center = (const int*)d_in[2];
    const float* WQ = (const float*)d_in[5];
    const float* WK = (const float*)d_in[6];
    const float* WV = (const float*)d_in[7];
    const float* WO = (const float*)d_in[8];
    float* out = (float*)d_out;
    int N = in_sizes[0] / 128;
    int E = in_sizes[1] / 128;

    float* gQ;
    cudaGetSymbolAddress((void**)&gQ, g_Q);

    k_init_rs<<<(N + 256) / 256, 256>>>(N, E);
    k_bounds<<<(E + 255) / 256, 256>>>(center, E);
    k_dense128<<<592, 512>>>(hV, WQ, gQ, N);   // Q = h_V @ W_Q^T
    k_qk<<<592, 512>>>(gQ, WK, N);             // qk per node/head
    k_node<<<N, 256>>>(hE, N);                 // softmax + aggregate (single h_E pass)
    k_vagg<<<592, 512>>>(WV, gQ, N);           // TMP = W_V applied per head
    k_dense128<<<592, 512>>>(gQ, WO, out, N);  // out = TMP @ W_O^T
}

// round 9
// speedup vs baseline: 1.2347x; 1.2347x over previous
#include <cuda_runtime.h>
#include <cstdint>
#include <cstddef>

#define NMAX 50000
#define EMAX 1600000
#define NEG_BIG (-1.0e30f)

__device__ float g_Q[(size_t)NMAX * 128];    // Q scratch, reused as TMP
__device__ float g_qk[(size_t)NMAX * 512];   // [n][h*128+j]
__device__ float g_agg[(size_t)NMAX * 512];  // [n][h*128+j] normalized aggregate
__device__ int   g_rs[NMAX + 1];

typedef unsigned long long ull;
__device__ __forceinline__ ull f2_pack(float x, float y) {
    ull r; asm("mov.b64 %0, {%1,%2};" : "=l"(r) : "f"(x), "f"(y)); return r;
}
__device__ __forceinline__ void f2_fma(ull& a, ull b, ull c) {
    asm("fma.rn.f32x2 %0, %1, %2, %0;" : "+l"(a) : "l"(b), "l"(c));
}
__device__ __forceinline__ void f2_mul(ull& a, ull b) {
    asm("mul.rn.f32x2 %0, %0, %1;" : "+l"(a) : "l"(b));
}
__device__ __forceinline__ float f2_sum(ull v) {
    float x, y; asm("mov.b64 {%0,%1}, %2;" : "=f"(x), "=f"(y) : "l"(v)); return x + y;
}

// ---- segment bounds from sorted center_id ----
__global__ void k_init_rs(int N, int E) {
    int t = blockIdx.x * blockDim.x + threadIdx.x;
    if (t <= N) g_rs[t] = E;
}
__global__ void k_bounds(const int* __restrict__ center, int E) {
    int e = blockIdx.x * blockDim.x + threadIdx.x;
    if (e >= E) return;
    int c = center[e];
    int p = (e == 0) ? -1 : center[e - 1];
    for (int n = p + 1; n <= c; n++) g_rs[n] = e;
}

#define RB 4  // rows per iteration in dense kernels

// ---- Y[n,i] = sum_k X[n,k]*W[i*128+k] ----
__global__ __launch_bounds__(512, 2) void k_dense128(const float* __restrict__ X,
                                                     const float* __restrict__ W,
                                                     float* __restrict__ Y, int N) {
    __shared__ alignas(16) float x_s[RB][128];
    __shared__ float part_s[RB][4][128];
    int t = threadIdx.x, i = t & 127, kq = t >> 7;
    ull w2[16];
    const float* wp = W + (size_t)i * 128 + kq * 32;
#pragma unroll
    for (int c = 0; c < 16; c++) { float2 v = *(const float2*)(wp + 2 * c); w2[c] = f2_pack(v.x, v.y); }
    for (int base = blockIdx.x * RB; base < N; base += gridDim.x * RB) {
        if (t < RB * 32) {
            int r = t >> 5, c4 = t & 31, n = base + r;
            float4 v = (n < N) ? *(const float4*)(X + (size_t)n * 128 + c4 * 4)
                               : make_float4(0.f, 0.f, 0.f, 0.f);
            *(float4*)(&x_s[r][c4 * 4]) = v;
        }
        __syncthreads();
        ull a[RB];
#pragma unroll
        for (int r = 0; r < RB; r++) a[r] = 0ull;
#pragma unroll
        for (int c = 0; c < 16; c++) {
#pragma unroll
            for (int r = 0; r < RB; r++) {
                ull u = *(const ull*)(&x_s[r][kq * 32 + 2 * c]);
                f2_fma(a[r], w2[c], u);
            }
        }
#pragma unroll
        for (int r = 0; r < RB; r++) part_s[r][kq][i] = f2_sum(a[r]);
        __syncthreads();
        {
            int r = t >> 7, ii = t & 127, n = base + r;
            if (n < N)
                Y[(size_t)n * 128 + ii] = part_s[r][0][ii] + part_s[r][1][ii] +
                                          part_s[r][2][ii] + part_s[r][3][ii];
        }
        __syncthreads();
    }
}

// ---- qk[n,h*128+j] = SC * sum_d Q[n,h*32+d]*W_K[(h*32+d)*128+j] ----
__global__ __launch_bounds__(512, 2) void k_qk(const float* __restrict__ Q,
                                               const float* __restrict__ WK, int N) {
    __shared__ alignas(16) float q_s[RB][128];
    int t = threadIdx.x, h = t >> 7, j = t & 127;
    ull w2[16];
#pragma unroll
    for (int c = 0; c < 16; c++)
        w2[c] = f2_pack(WK[(size_t)(h * 32 + 2 * c) * 128 + j],
                        WK[(size_t)(h * 32 + 2 * c + 1) * 128 + j]);
    const float SC = 0.17677669529663687f;  // 1/sqrt(32)
    for (int base = blockIdx.x * RB; base < N; base += gridDim.x * RB) {
        if (t < RB * 32) {
            int r = t >> 5, c4 = t & 31, n = base + r;
            float4 v = (n < N) ? *(const float4*)(Q + (size_t)n * 128 + c4 * 4)
                               : make_float4(0.f, 0.f, 0.f, 0.f);
            *(float4*)(&q_s[r][c4 * 4]) = v;
        }
        __syncthreads();
        ull a[RB];
#pragma unroll
        for (int r = 0; r < RB; r++) a[r] = 0ull;
#pragma unroll
        for (int c = 0; c < 16; c++) {
#pragma unroll
            for (int r = 0; r < RB; r++) {
                ull u = *(const ull*)(&q_s[r][h * 32 + 2 * c]);
                f2_fma(a[r], w2[c], u);
            }
        }
#pragma unroll
        for (int r = 0; r < RB; r++)
            if (base + r < N) g_qk[(size_t)(base + r) * 512 + t] = f2_sum(a[r]) * SC;
        __syncthreads();
    }
}

// ---- TMP[n,i] = sum_j W_V[i*128+j] * AG[n,(i>>5)*128+j] ----
__global__ __launch_bounds__(512, 2) void k_vagg(const float* __restrict__ WV,
                                                 float* __restrict__ TMP, int N) {
    __shared__ alignas(16) float ag_s[RB][512];
    __shared__ float part_s[RB][4][128];
    int t = threadIdx.x, i = t & 127, kq = t >> 7, h = i >> 5;
    ull w2[16];
    const float* wp = WV + (size_t)i * 128 + kq * 32;
#pragma unroll
    for (int c = 0; c < 16; c++) { float2 v = *(const float2*)(wp + 2 * c); w2[c] = f2_pack(v.x, v.y); }
    for (int base = blockIdx.x * RB; base < N; base += gridDim.x * RB) {
        {
            int r = t >> 7, c4 = t & 127, n = base + r;
            float4 v = (n < N) ? *(const float4*)(g_agg + (size_t)n * 512 + c4 * 4)
                               : make_float4(0.f, 0.f, 0.f, 0.f);
            *(float4*)(&ag_s[r][c4 * 4]) = v;
        }
        __syncthreads();
        ull a[RB];
#pragma unroll
        for (int r = 0; r < RB; r++) a[r] = 0ull;
#pragma unroll
        for (int c = 0; c < 16; c++) {
#pragma unroll
            for (int r = 0; r < RB; r++) {
                ull u = *(const ull*)(&ag_s[r][h * 128 + kq * 32 + 2 * c]);
                f2_fma(a[r], w2[c], u);
            }
        }
#pragma unroll
        for (int r = 0; r < RB; r++) part_s[r][kq][i] = f2_sum(a[r]);
        __syncthreads();
        {
            int r = t >> 7, ii = t & 127, n = base + r;
            if (n < N)
                TMP[(size_t)n * 128 + ii] = part_s[r][0][ii] + part_s[r][1][ii] +
                                            part_s[r][2][ii] + part_s[r][3][ii];
        }
        __syncthreads();
    }
}

// ---- per-node single pass over h_E: SMEM online softmax + aggregation ----
// warp w: head hh2=w&3, half jh=w>>2; lane l owns adjacent cols (jh*64+2l, +1)
#define CH 40
#define PADR 132
__global__ __launch_bounds__(256) void k_node(const float* __restrict__ hE, int N) {
    __shared__ alignas(16) float hE_s[CH * PADR];  // 21.1 KB
    __shared__ alignas(16) float qk_s[4 * PADR];
    __shared__ alignas(16) float lgT[4 * 68];
    __shared__ alignas(16) float pT[4 * 68];
    __shared__ float m_s[4], s_s[4], sc_s[4];
    int t = threadIdx.x;
    int n = blockIdx.x;
    if (n >= N) return;
    int beg = g_rs[n], end = g_rs[n + 1];

    for (int idx = t; idx < 512; idx += 256) {
        int hh = idx >> 7, j = idx & 127;
        qk_s[hh * PADR + j] = g_qk[(size_t)n * 512 + idx];
    }
    if (t < 4) { m_s[t] = NEG_BIG; s_s[t] = 0.f; }
    int w = t >> 5, l = t & 31;
    int hh2 = w & 3, jh = w >> 2;
    int jc = jh * 64 + 2 * l;          // adjacent column pair
    ull accP = 0ull;                   // packed accumulator (cols jc, jc+1)
    __syncthreads();

    for (int cs = beg; cs < end; cs += CH) {
        int cnt = min(CH, end - cs);
        for (int idx = t; idx < cnt * 32; idx += 256) {
            int r = idx >> 5, c4 = idx & 31;
            float4 v = *(const float4*)(hE + (size_t)(cs + r) * 128 + c4 * 4);
            *(float4*)(&hE_s[r * PADR + c4 * 4]) = v;
        }
        __syncthreads();
        {   // logits: thread (e = t>>2, head = t&3); 4 lanes share row -> LDS broadcast
            int e = t >> 2, hq = t & 3;
            float lg = NEG_BIG;
            if (e < cnt) {
                ull acc = 0ull;
                const float* qp = &qk_s[hq * PADR];
                const float* xp = &hE_s[e * PADR];
#pragma unroll
                for (int jj = 0; jj < 32; jj++) {
                    float4 q4 = *(const float4*)(qp + jj * 4);
                    float4 x4 = *(const float4*)(xp + jj * 4);
                    f2_fma(acc, f2_pack(q4.x, q4.y), f2_pack(x4.x, x4.y));
                    f2_fma(acc, f2_pack(q4.z, q4.w), f2_pack(x4.z, x4.w));
                }
                lg = f2_sum(acc);
            }
            lgT[hq * 68 + e] = lg;
        }
        __syncthreads();
        if (t < 128) {  // per-head running max + rescale factor
            int wh = t >> 5, l2 = t & 31;
            float v = fmaxf(lgT[wh * 68 + l2], lgT[wh * 68 + l2 + 32]);
#pragma unroll
            for (int o = 16; o; o >>= 1) v = fmaxf(v, __shfl_xor_sync(0xffffffffu, v, o));
            if (l2 == 0) {
                float old = m_s[wh], nm = fmaxf(old, v);
                sc_s[wh] = __expf(old - nm);
                m_s[wh] = nm;
            }
        }
        __syncthreads();
        {   // p = exp(l - m), zero-padded
            int e = t >> 2, hq = t & 3;
            pT[hq * 68 + e] = (e < cnt) ? __expf(lgT[hq * 68 + e] - m_s[hq]) : 0.f;
        }
        __syncthreads();
        if (t < 128) {  // running sum
            int wh = t >> 5, l2 = t & 31;
            float v = pT[wh * 68 + l2] + pT[wh * 68 + l2 + 32];
#pragma unroll
            for (int o = 16; o; o >>= 1) v += __shfl_xor_sync(0xffffffffu, v, o);
            if (l2 == 0) s_s[wh] = s_s[wh] * sc_s[wh] + v;
        }
        {   // accumulate: 1 LDS.64 + 1 FFMA2 per edge per warp
            float sc = sc_s[hh2];
            f2_mul(accP, f2_pack(sc, sc));
            const float* pp = &pT[hh2 * 68];
#pragma unroll 4
            for (int e = 0; e < cnt; e++) {
                float p = pp[e];
                ull x2 = *(const ull*)(&hE_s[e * PADR + jc]);
                f2_fma(accP, f2_pack(p, p), x2);
            }
        }
        __syncthreads();
    }
    float inv = (end > beg) ? (1.0f / s_s[hh2]) : 0.f;
    float aLo, aHi;
    asm("mov.b64 {%0,%1}, %2;" : "=f"(aLo), "=f"(aHi) : "l"(accP));
    *(float2*)(g_agg + (size_t)n * 512 + hh2 * 128 + jc) =
        make_float2(aLo * inv, aHi * inv);
}

extern "C" void kernel_launch(void* const* d_in, const int* in_sizes, int n_in,
                              void* d_out, int out_size) {
    const float* hV = (const float*)d_in[0];
    const float* hE = (const float*)d_in[1];
    const int* center = (const int*)d_in[2];
    const float* WQ = (const float*)d_in[5];
    const float* WK = (const float*)d_in[6];
    const float* WV = (const float*)d_in[7];
    const float* WO = (const float*)d_in[8];
    float* out = (float*)d_out;
    int N = in_sizes[0] / 128;
    int E = in_sizes[1] / 128;

    float* gQ;
    cudaGetSymbolAddress((void**)&gQ, g_Q);

    k_init_rs<<<(N + 256) / 256, 256>>>(N, E);
    k_bounds<<<(E + 255) / 256, 256>>>(center, E);
    k_dense128<<<592, 512>>>(hV, WQ, gQ, N);   // Q = h_V @ W_Q^T
    k_qk<<<592, 512>>>(gQ, WK, N);             // qk per node/head
    k_node<<<N, 256>>>(hE, N);                 // softmax + aggregate (single h_E pass)
    k_vagg<<<592, 512>>>(WV, gQ, N);           // TMP = W_V applied per head
    k_dense128<<<592, 512>>>(gQ, WO, out, N);  // out = TMP @ W_O^T
}

// round 10
// speedup vs baseline: 1.3077x; 1.0591x over previous
#include <cuda_runtime.h>
#include <cstdint>
#include <cstddef>

#define NMAX 50000
#define EMAX 1600000
#define NEG_BIG (-1.0e30f)

__device__ float g_Q[(size_t)NMAX * 128];    // Q scratch, reused as TMP
__device__ float g_qk[(size_t)NMAX * 512];   // [n][h*128+j]
__device__ float g_agg[(size_t)NMAX * 512];  // [n][h*128+j] normalized aggregate
__device__ int   g_rs[NMAX + 1];

typedef unsigned long long ull;
__device__ __forceinline__ ull f2_pack(float x, float y) {
    ull r; asm("mov.b64 %0, {%1,%2};" : "=l"(r) : "f"(x), "f"(y)); return r;
}
__device__ __forceinline__ void f2_fma(ull& a, ull b, ull c) {
    asm("fma.rn.f32x2 %0, %1, %2, %0;" : "+l"(a) : "l"(b), "l"(c));
}
__device__ __forceinline__ float f2_sum(ull v) {
    float x, y; asm("mov.b64 {%0,%1}, %2;" : "=f"(x), "=f"(y) : "l"(v)); return x + y;
}

// ---- segment bounds from sorted center_id ----
__global__ void k_init_rs(int N, int E) {
    int t = blockIdx.x * blockDim.x + threadIdx.x;
    if (t <= N) g_rs[t] = E;
}
__global__ void k_bounds(const int* __restrict__ center, int E) {
    int e = blockIdx.x * blockDim.x + threadIdx.x;
    if (e >= E) return;
    int c = center[e];
    int p = (e == 0) ? -1 : center[e - 1];
    for (int n = p + 1; n <= c; n++) g_rs[n] = e;
}

#define RB 4  // rows per iteration in dense kernels

// ---- Y[n,i] = sum_k X[n,k]*W[i*128+k] ----
__global__ __launch_bounds__(512, 2) void k_dense128(const float* __restrict__ X,
                                                     const float* __restrict__ W,
                                                     float* __restrict__ Y, int N) {
    __shared__ alignas(16) float x_s[RB][128];
    __shared__ float part_s[RB][4][128];
    int t = threadIdx.x, i = t & 127, kq = t >> 7;
    ull w2[16];
    const float* wp = W + (size_t)i * 128 + kq * 32;
#pragma unroll
    for (int c = 0; c < 16; c++) { float2 v = *(const float2*)(wp + 2 * c); w2[c] = f2_pack(v.x, v.y); }
    for (int base = blockIdx.x * RB; base < N; base += gridDim.x * RB) {
        if (t < RB * 32) {
            int r = t >> 5, c4 = t & 31, n = base + r;
            float4 v = (n < N) ? *(const float4*)(X + (size_t)n * 128 + c4 * 4)
                               : make_float4(0.f, 0.f, 0.f, 0.f);
            *(float4*)(&x_s[r][c4 * 4]) = v;
        }
        __syncthreads();
        ull a[RB];
#pragma unroll
        for (int r = 0; r < RB; r++) a[r] = 0ull;
#pragma unroll
        for (int c = 0; c < 16; c++) {
#pragma unroll
            for (int r = 0; r < RB; r++) {
                ull u = *(const ull*)(&x_s[r][kq * 32 + 2 * c]);
                f2_fma(a[r], w2[c], u);
            }
        }
#pragma unroll
        for (int r = 0; r < RB; r++) part_s[r][kq][i] = f2_sum(a[r]);
        __syncthreads();
        {
            int r = t >> 7, ii = t & 127, n = base + r;
            if (n < N)
                Y[(size_t)n * 128 + ii] = part_s[r][0][ii] + part_s[r][1][ii] +
                                          part_s[r][2][ii] + part_s[r][3][ii];
        }
        __syncthreads();
    }
}

// ---- qk[n,h*128+j] = SC * sum_d Q[n,h*32+d]*W_K[(h*32+d)*128+j] ----
__global__ __launch_bounds__(512, 2) void k_qk(const float* __restrict__ Q,
                                               const float* __restrict__ WK, int N) {
    __shared__ alignas(16) float q_s[RB][128];
    int t = threadIdx.x, h = t >> 7, j = t & 127;
    ull w2[16];
#pragma unroll
    for (int c = 0; c < 16; c++)
        w2[c] = f2_pack(WK[(size_t)(h * 32 + 2 * c) * 128 + j],
                        WK[(size_t)(h * 32 + 2 * c + 1) * 128 + j]);
    const float SC = 0.17677669529663687f;  // 1/sqrt(32)
    for (int base = blockIdx.x * RB; base < N; base += gridDim.x * RB) {
        if (t < RB * 32) {
            int r = t >> 5, c4 = t & 31, n = base + r;
            float4 v = (n < N) ? *(const float4*)(Q + (size_t)n * 128 + c4 * 4)
                               : make_float4(0.f, 0.f, 0.f, 0.f);
            *(float4*)(&q_s[r][c4 * 4]) = v;
        }
        __syncthreads();
        ull a[RB];
#pragma unroll
        for (int r = 0; r < RB; r++) a[r] = 0ull;
#pragma unroll
        for (int c = 0; c < 16; c++) {
#pragma unroll
            for (int r = 0; r < RB; r++) {
                ull u = *(const ull*)(&q_s[r][h * 32 + 2 * c]);
                f2_fma(a[r], w2[c], u);
            }
        }
#pragma unroll
        for (int r = 0; r < RB; r++)
            if (base + r < N) g_qk[(size_t)(base + r) * 512 + t] = f2_sum(a[r]) * SC;
        __syncthreads();
    }
}

// ---- TMP[n,i] = sum_j W_V[i*128+j] * AG[n,(i>>5)*128+j] ----
__global__ __launch_bounds__(512, 2) void k_vagg(const float* __restrict__ WV,
                                                 float* __restrict__ TMP, int N) {
    __shared__ alignas(16) float ag_s[RB][512];
    __shared__ float part_s[RB][4][128];
    int t = threadIdx.x, i = t & 127, kq = t >> 7, h = i >> 5;
    ull w2[16];
    const float* wp = WV + (size_t)i * 128 + kq * 32;
#pragma unroll
    for (int c = 0; c < 16; c++) { float2 v = *(const float2*)(wp + 2 * c); w2[c] = f2_pack(v.x, v.y); }
    for (int base = blockIdx.x * RB; base < N; base += gridDim.x * RB) {
        {
            int r = t >> 7, c4 = t & 127, n = base + r;
            float4 v = (n < N) ? *(const float4*)(g_agg + (size_t)n * 512 + c4 * 4)
                               : make_float4(0.f, 0.f, 0.f, 0.f);
            *(float4*)(&ag_s[r][c4 * 4]) = v;
        }
        __syncthreads();
        ull a[RB];
#pragma unroll
        for (int r = 0; r < RB; r++) a[r] = 0ull;
#pragma unroll
        for (int c = 0; c < 16; c++) {
#pragma unroll
            for (int r = 0; r < RB; r++) {
                ull u = *(const ull*)(&ag_s[r][h * 128 + kq * 32 + 2 * c]);
                f2_fma(a[r], w2[c], u);
            }
        }
#pragma unroll
        for (int r = 0; r < RB; r++) part_s[r][kq][i] = f2_sum(a[r]);
        __syncthreads();
        {
            int r = t >> 7, ii = t & 127, n = base + r;
            if (n < N)
                TMP[(size_t)n * 128 + ii] = part_s[r][0][ii] + part_s[r][1][ii] +
                                            part_s[r][2][ii] + part_s[r][3][ii];
        }
        __syncthreads();
    }
}

// ---- per-node single pass over h_E: SMEM online softmax + aggregation ----
#define CH 40
#define PADR 132
__global__ __launch_bounds__(256) void k_node(const float* __restrict__ hE, int N) {
    __shared__ alignas(16) float hE_s[CH * PADR];  // 21.1 KB
    __shared__ alignas(16) float qk_s[4 * PADR];
    __shared__ alignas(16) float lgT[4 * 68];
    __shared__ alignas(16) float pT[4 * 68];
    __shared__ float m_s[4], s_s[4], sc_s[4];
    int t = threadIdx.x;
    int n = blockIdx.x;
    if (n >= N) return;
    int beg = g_rs[n], end = g_rs[n + 1];

    for (int idx = t; idx < 512; idx += 256) {
        int hh = idx >> 7, j = idx & 127;
        qk_s[hh * PADR + j] = g_qk[(size_t)n * 512 + idx];
    }
    if (t < 4) { m_s[t] = NEG_BIG; s_s[t] = 0.f; }
    int w = t >> 5, l = t & 31;
    int hh2 = w & 3, jh = w >> 2, j1 = jh * 64 + l;
    float accLo = 0.f, accHi = 0.f;
    __syncthreads();

    for (int cs = beg; cs < end; cs += CH) {
        int cnt = min(CH, end - cs);
        for (int idx = t; idx < cnt * 32; idx += 256) {
            int r = idx >> 5, c4 = idx & 31;
            float4 v = *(const float4*)(hE + (size_t)(cs + r) * 128 + c4 * 4);
            *(float4*)(&hE_s[r * PADR + c4 * 4]) = v;
        }
        __syncthreads();
        {   // logits: thread (e = t>>2, head = t&3); LDS.128 -> FFMA2, no packs
            int e = t >> 2, hq = t & 3;
            float lg = NEG_BIG;
            if (e < cnt) {
                ull acc = 0ull;
                const float* qp = &qk_s[hq * PADR];
                const float* xp = &hE_s[e * PADR];
#pragma unroll
                for (int jj = 0; jj < 32; jj++) {
                    ulonglong2 q4 = *(const ulonglong2*)(qp + jj * 4);
                    ulonglong2 x4 = *(const ulonglong2*)(xp + jj * 4);
                    f2_fma(acc, q4.x, x4.x);
                    f2_fma(acc, q4.y, x4.y);
                }
                lg = f2_sum(acc);
            }
            lgT[hq * 68 + e] = lg;
        }
        __syncthreads();
        if (t < 128) {  // per-head running max + rescale factor
            int wh = t >> 5, l2 = t & 31;
            float v = fmaxf(lgT[wh * 68 + l2], lgT[wh * 68 + l2 + 32]);
#pragma unroll
            for (int o = 16; o; o >>= 1) v = fmaxf(v, __shfl_xor_sync(0xffffffffu, v, o));
            if (l2 == 0) {
                float old = m_s[wh], nm = fmaxf(old, v);
                sc_s[wh] = __expf(old - nm);
                m_s[wh] = nm;
            }
        }
        __syncthreads();
        {   // p = exp(l - m), zero-padded
            int e = t >> 2, hq = t & 3;
            pT[hq * 68 + e] = (e < cnt) ? __expf(lgT[hq * 68 + e] - m_s[hq]) : 0.f;
        }
        __syncthreads();
        if (t < 128) {  // running sum
            int wh = t >> 5, l2 = t & 31;
            float v = pT[wh * 68 + l2] + pT[wh * 68 + l2 + 32];
#pragma unroll
            for (int o = 16; o; o >>= 1) v += __shfl_xor_sync(0xffffffffu, v, o);
            if (l2 == 0) s_s[wh] = s_s[wh] * sc_s[wh] + v;
        }
        {   // accumulate: two independent scalar FMA chains, p broadcast
            float sc = sc_s[hh2];
            accLo *= sc; accHi *= sc;
            const float* pp = &pT[hh2 * 68];
#pragma unroll 4
            for (int e = 0; e < cnt; e++) {
                float p = pp[e];
                accLo = fmaf(p, hE_s[e * PADR + j1], accLo);
                accHi = fmaf(p, hE_s[e * PADR + j1 + 32], accHi);
            }
        }
        __syncthreads();
    }
    float inv = (end > beg) ? (1.0f / s_s[hh2]) : 0.f;
    g_agg[(size_t)n * 512 + hh2 * 128 + j1]      = accLo * inv;
    g_agg[(size_t)n * 512 + hh2 * 128 + j1 + 32] = accHi * inv;
}

extern "C" void kernel_launch(void* const* d_in, const int* in_sizes, int n_in,
                              void* d_out, int out_size) {
    const float* hV = (const float*)d_in[0];
    const float* hE = (const float*)d_in[1];
    const int* center = (const int*)d_in[2];
    const float* WQ = (const float*)d_in[5];
    const float* WK = (const float*)d_in[6];
    const float* WV = (const float*)d_in[7];
    const float* WO = (const float*)d_in[8];
    float* out = (float*)d_out;
    int N = in_sizes[0] / 128;
    int E = in_sizes[1] / 128;

    float* gQ;
    cudaGetSymbolAddress((void**)&gQ, g_Q);

    k_init_rs<<<(N + 256) / 256, 256>>>(N, E);
    k_bounds<<<(E + 255) / 256, 256>>>(center, E);
    k_dense128<<<592, 512>>>(hV, WQ, gQ, N);   // Q = h_V @ W_Q^T
    k_qk<<<592, 512>>>(gQ, WK, N);             // qk per node/head
    k_node<<<N, 256>>>(hE, N);                 // softmax + aggregate (single h_E pass)
    k_vagg<<<592, 512>>>(WV, gQ, N);           // TMP = W_V applied per head
    k_dense128<<<592, 512>>>(gQ, WO, out, N);  // out = TMP @ W_O^T
}

// round 12
// speedup vs baseline: 1.4398x; 1.1010x over previous
#include <cuda_runtime.h>
#include <cuda_bf16.h>
#include <cstdint>
#include <cstddef>

#define NMAX 50000
#define NEG_BIG (-1.0e30f)

__device__ float g_qk[(size_t)NMAX * 512];   // [n][h*128+j]
__device__ float g_agg[(size_t)NMAX * 512];  // [n][h*128+j]
__device__ int   g_rs[NMAX + 1];
__device__ __nv_bfloat16 g_M1hi[512 * 128], g_M1lo[512 * 128];  // [o][k]
__device__ __nv_bfloat16 g_M2hi[128 * 512], g_M2lo[128 * 512];  // [o][kk]

typedef unsigned long long ull;
__device__ __forceinline__ void f2_fma(ull& a, ull b, ull c) {
    asm("fma.rn.f32x2 %0, %1, %2, %0;" : "+l"(a) : "l"(b), "l"(c));
}
__device__ __forceinline__ float f2_sum(ull v) {
    float x, y; asm("mov.b64 {%0,%1}, %2;" : "=f"(x), "=f"(y) : "l"(v)); return x + y;
}

__device__ __forceinline__ void mma_bf16(float* c, const uint32_t* a, const uint32_t* b) {
    asm volatile(
        "mma.sync.aligned.m16n8k16.row.col.f32.bf16.bf16.f32 "
        "{%0,%1,%2,%3}, {%4,%5,%6,%7}, {%8,%9}, {%0,%1,%2,%3};"
        : "+f"(c[0]), "+f"(c[1]), "+f"(c[2]), "+f"(c[3])
        : "r"(a[0]), "r"(a[1]), "r"(a[2]), "r"(a[3]), "r"(b[0]), "r"(b[1]));
}

// ---- segment bounds ----
__global__ void k_init_rs(int N, int E) {
    int t = blockIdx.x * blockDim.x + threadIdx.x;
    if (t <= N) g_rs[t] = E;
}
__global__ void k_bounds(const int* __restrict__ center, int E) {
    int e = blockIdx.x * blockDim.x + threadIdx.x;
    if (e >= E) return;
    int c = center[e];
    int p = (e == 0) ? -1 : center[e - 1];
    for (int n = p + 1; n <= c; n++) g_rs[n] = e;
}

// ---- combined weights (bf16 hi/lo) ----
// M1[k][o=h*128+j] = SC * sum_d WQ[h*32+d][k]*WK[h*32+d][j]; stored [o][k]
__global__ void k_m1(const float* __restrict__ WQ, const float* __restrict__ WK) {
    int k = blockIdx.x, o = threadIdx.x, h = o >> 7, j = o & 127;
    float s = 0.f;
#pragma unroll 8
    for (int d = 0; d < 32; d++)
        s += WQ[(size_t)(h * 32 + d) * 128 + k] * WK[(size_t)(h * 32 + d) * 128 + j];
    s *= 0.17677669529663687f;
    __nv_bfloat16 hi = __float2bfloat16(s);
    g_M1hi[o * 128 + k] = hi;
    g_M1lo[o * 128 + k] = __float2bfloat16(s - __bfloat162float(hi));
}
// M2[kk=h*128+j][o] = sum_d WO[o][h*32+d]*WV[h*32+d][j]; stored [o][kk]
__global__ void k_m2(const float* __restrict__ WO, const float* __restrict__ WV) {
    int o = blockIdx.x, kk = threadIdx.x, h = kk >> 7, j = kk & 127;
    float s = 0.f;
#pragma unroll 8
    for (int d = 0; d < 32; d++)
        s += WO[(size_t)o * 128 + h * 32 + d] * WV[(size_t)(h * 32 + d) * 128 + j];
    __nv_bfloat16 hi = __float2bfloat16(s);
    g_M2hi[o * 512 + kk] = hi;
    g_M2lo[o * 512 + kk] = __float2bfloat16(s - __bfloat162float(hi));
}

#define PAD 136
#define SMEM_GEMM (4 * 128 * PAD * 2)  // Ah, Al, Bh, Bl = 139264 bytes

// convert one fp32 value pair to bf16 hi/lo pairs and store
__device__ __forceinline__ void store_hl(__nv_bfloat16* Ah, __nv_bfloat16* Al,
                                         int off, float2 v) {
    __nv_bfloat16 hx = __float2bfloat16(v.x), hy = __float2bfloat16(v.y);
    *(__nv_bfloat162*)(Ah + off) = __halves2bfloat162(hx, hy);
    __nv_bfloat16 lx = __float2bfloat16(v.x - __bfloat162float(hx));
    __nv_bfloat16 ly = __float2bfloat16(v.y - __bfloat162float(hy));
    *(__nv_bfloat162*)(Al + off) = __halves2bfloat162(lx, ly);
}

// ---- qk = hV @ M1  (M=128-row tiles, N=512 in 4 chunks, K=128) ----
__global__ __launch_bounds__(512) void k_gemm_qk(const float* __restrict__ X, int N) {
    extern __shared__ char sm[];
    __nv_bfloat16* Ah = (__nv_bfloat16*)sm;
    __nv_bfloat16* Al = Ah + 128 * PAD;
    __nv_bfloat16* Bh = Al + 128 * PAD;
    __nv_bfloat16* Bl = Bh + 128 * PAD;
    int t = threadIdx.x, lane = t & 31, wid = t >> 5;
    int wr = wid >> 1, wc = wid & 1, g = lane >> 2, tig = lane & 3;
    int n0 = blockIdx.x * 128;

    for (int idx = t; idx < 128 * 64; idx += 512) {
        int r = idx >> 6, kp = (idx & 63) * 2;
        float2 v = (n0 + r < N) ? *(const float2*)(X + (size_t)(n0 + r) * 128 + kp)
                                : make_float2(0.f, 0.f);
        store_hl(Ah, Al, r * PAD + kp, v);
    }
    int ra = 16 * wr + g;
    for (int nc = 0; nc < 4; nc++) {
        if (nc) __syncthreads();
        for (int idx = t; idx < 128 * 16; idx += 512) {
            int r = idx >> 4, k8 = (idx & 15) * 8;
            *(uint4*)(Bh + r * PAD + k8) = *(const uint4*)(g_M1hi + (size_t)(nc * 128 + r) * 128 + k8);
            *(uint4*)(Bl + r * PAD + k8) = *(const uint4*)(g_M1lo + (size_t)(nc * 128 + r) * 128 + k8);
        }
        __syncthreads();
        float acc[8][4];
#pragma unroll
        for (int nt = 0; nt < 8; nt++)
#pragma unroll
            for (int c = 0; c < 4; c++) acc[nt][c] = 0.f;
#pragma unroll
        for (int ks = 0; ks < 8; ks++) {
            int k0 = 16 * ks + tig * 2;
            uint32_t ah[4], al[4];
            ah[0] = *(const uint32_t*)(Ah + ra * PAD + k0);
            ah[1] = *(const uint32_t*)(Ah + (ra + 8) * PAD + k0);
            ah[2] = *(const uint32_t*)(Ah + ra * PAD + k0 + 8);
            ah[3] = *(const uint32_t*)(Ah + (ra + 8) * PAD + k0 + 8);
            al[0] = *(const uint32_t*)(Al + ra * PAD + k0);
            al[1] = *(const uint32_t*)(Al + (ra + 8) * PAD + k0);
            al[2] = *(const uint32_t*)(Al + ra * PAD + k0 + 8);
            al[3] = *(const uint32_t*)(Al + (ra + 8) * PAD + k0 + 8);
#pragma unroll
            for (int nt = 0; nt < 8; nt++) {
                int nb = 64 * wc + 8 * nt + g;
                uint32_t bh[2], bl[2];
                bh[0] = *(const uint32_t*)(Bh + nb * PAD + k0);
                bh[1] = *(const uint32_t*)(Bh + nb * PAD + k0 + 8);
                bl[0] = *(const uint32_t*)(Bl + nb * PAD + k0);
                bl[1] = *(const uint32_t*)(Bl + nb * PAD + k0 + 8);
                mma_bf16(acc[nt], ah, bh);
                mma_bf16(acc[nt], ah, bl);
                mma_bf16(acc[nt], al, bh);
            }
        }
        int r0 = n0 + ra;
#pragma unroll
        for (int nt = 0; nt < 8; nt++) {
            int col = nc * 128 + 64 * wc + 8 * nt + tig * 2;
            if (r0 < N)
                *(float2*)(g_qk + (size_t)r0 * 512 + col) = make_float2(acc[nt][0], acc[nt][1]);
            if (r0 + 8 < N)
                *(float2*)(g_qk + (size_t)(r0 + 8) * 512 + col) = make_float2(acc[nt][2], acc[nt][3]);
        }
    }
}

// ---- out = agg @ M2  (M=128-row tiles, N=128, K=512 in 4 chunks) ----
__global__ __launch_bounds__(512) void k_gemm_out(float* __restrict__ OUT, int N) {
    extern __shared__ char sm[];
    __nv_bfloat16* Ah = (__nv_bfloat16*)sm;
    __nv_bfloat16* Al = Ah + 128 * PAD;
    __nv_bfloat16* Bh = Al + 128 * PAD;
    __nv_bfloat16* Bl = Bh + 128 * PAD;
    int t = threadIdx.x, lane = t & 31, wid = t >> 5;
    int wr = wid >> 1, wc = wid & 1, g = lane >> 2, tig = lane & 3;
    int n0 = blockIdx.x * 128;
    int ra = 16 * wr + g;

    float acc[8][4];
#pragma unroll
    for (int nt = 0; nt < 8; nt++)
#pragma unroll
        for (int c = 0; c < 4; c++) acc[nt][c] = 0.f;

    for (int kc = 0; kc < 4; kc++) {
        if (kc) __syncthreads();
        for (int idx = t; idx < 128 * 64; idx += 512) {
            int r = idx >> 6, kp = (idx & 63) * 2;
            float2 v = (n0 + r < N)
                ? *(const float2*)(g_agg + (size_t)(n0 + r) * 512 + kc * 128 + kp)
                : make_float2(0.f, 0.f);
            store_hl(Ah, Al, r * PAD + kp, v);
        }
        for (int idx = t; idx < 128 * 16; idx += 512) {
            int r = idx >> 4, k8 = (idx & 15) * 8;
            *(uint4*)(Bh + r * PAD + k8) = *(const uint4*)(g_M2hi + (size_t)r * 512 + kc * 128 + k8);
            *(uint4*)(Bl + r * PAD + k8) = *(const uint4*)(g_M2lo + (size_t)r * 512 + kc * 128 + k8);
        }
        __syncthreads();
#pragma unroll
        for (int ks = 0; ks < 8; ks++) {
            int k0 = 16 * ks + tig * 2;
            uint32_t ah[4], al[4];
            ah[0] = *(const uint32_t*)(Ah + ra * PAD + k0);
            ah[1] = *(const uint32_t*)(Ah + (ra + 8) * PAD + k0);
            ah[2] = *(const uint32_t*)(Ah + ra * PAD + k0 + 8);
            ah[3] = *(const uint32_t*)(Ah + (ra + 8) * PAD + k0 + 8);
            al[0] = *(const uint32_t*)(Al + ra * PAD + k0);
            al[1] = *(const uint32_t*)(Al + (ra + 8) * PAD + k0);
            al[2] = *(const uint32_t*)(Al + ra * PAD + k0 + 8);
            al[3] = *(const uint32_t*)(Al + (ra + 8) * PAD + k0 + 8);
#pragma unroll
            for (int nt = 0; nt < 8; nt++) {
                int nb = 64 * wc + 8 * nt + g;
                uint32_t bh[2], bl[2];
                bh[0] = *(const uint32_t*)(Bh + nb * PAD + k0);
                bh[1] = *(const uint32_t*)(Bh + nb * PAD + k0 + 8);
                bl[0] = *(const uint32_t*)(Bl + nb * PAD + k0);
                bl[1] = *(const uint32_t*)(Bl + nb * PAD + k0 + 8);
                mma_bf16(acc[nt], ah, bh);
                mma_bf16(acc[nt], ah, bl);
                mma_bf16(acc[nt], al, bh);
            }
        }
    }
    int r0 = n0 + ra;
#pragma unroll
    for (int nt = 0; nt < 8; nt++) {
        int col = 64 * wc + 8 * nt + tig * 2;
        if (r0 < N)
            *(float2*)(OUT + (size_t)r0 * 128 + col) = make_float2(acc[nt][0], acc[nt][1]);
        if (r0 + 8 < N)
            *(float2*)(OUT + (size_t)(r0 + 8) * 128 + col) = make_float2(acc[nt][2], acc[nt][3]);
    }
}

// ---- per-node single pass over h_E: SMEM online softmax + aggregation ----
#define CH 40
#define PADR 132
__global__ __launch_bounds__(256) void k_node(const float* __restrict__ hE, int N) {
    __shared__ alignas(16) float hE_s[CH * PADR];
    __shared__ alignas(16) float qk_s[4 * PADR];
    __shared__ alignas(16) float lgT[4 * 68];
    __shared__ alignas(16) float pT[4 * 68];
    __shared__ float m_s[4], s_s[4], sc_s[4];
    int t = threadIdx.x;
    int n = blockIdx.x;
    if (n >= N) return;
    int beg = g_rs[n], end = g_rs[n + 1];

    for (int idx = t; idx < 512; idx += 256) {
        int hh = idx >> 7, j = idx & 127;
        qk_s[hh * PADR + j] = g_qk[(size_t)n * 512 + idx];
    }
    if (t < 4) { m_s[t] = NEG_BIG; s_s[t] = 0.f; }
    int w = t >> 5, l = t & 31;
    int hh2 = w & 3, jh = w >> 2, j1 = jh * 64 + l;
    float accLo = 0.f, accHi = 0.f;
    __syncthreads();

    for (int cs = beg; cs < end; cs += CH) {
        int cnt = min(CH, end - cs);
        for (int idx = t; idx < cnt * 32; idx += 256) {
            int r = idx >> 5, c4 = idx & 31;
            float4 v = *(const float4*)(hE + (size_t)(cs + r) * 128 + c4 * 4);
            *(float4*)(&hE_s[r * PADR + c4 * 4]) = v;
        }
        __syncthreads();
        {
            int e = t >> 2, hq = t & 3;
            float lg = NEG_BIG;
            if (e < cnt) {
                ull acc = 0ull;
                const float* qp = &qk_s[hq * PADR];
                const float* xp = &hE_s[e * PADR];
#pragma unroll
                for (int jj = 0; jj < 32; jj++) {
                    ulonglong2 q4 = *(const ulonglong2*)(qp + jj * 4);
                    ulonglong2 x4 = *(const ulonglong2*)(xp + jj * 4);
                    f2_fma(acc, q4.x, x4.x);
                    f2_fma(acc, q4.y, x4.y);
                }
                lg = f2_sum(acc);
            }
            lgT[hq * 68 + e] = lg;
        }
        __syncthreads();
        if (t < 128) {
            int wh = t >> 5, l2 = t & 31;
            float v = fmaxf(lgT[wh * 68 + l2], lgT[wh * 68 + l2 + 32]);
#pragma unroll
            for (int o = 16; o; o >>= 1) v = fmaxf(v, __shfl_xor_sync(0xffffffffu, v, o));
            if (l2 == 0) {
                float old = m_s[wh], nm = fmaxf(old, v);
                sc_s[wh] = __expf(old - nm);
                m_s[wh] = nm;
            }
        }
        __syncthreads();
        {
            int e = t >> 2, hq = t & 3;
            pT[hq * 68 + e] = (e < cnt) ? __expf(lgT[hq * 68 + e] - m_s[hq]) : 0.f;
        }
        __syncthreads();
        if (t < 128) {
            int wh = t >> 5, l2 = t & 31;
            float v = pT[wh * 68 + l2] + pT[wh * 68 + l2 + 32];
#pragma unroll
            for (int o = 16; o; o >>= 1) v += __shfl_xor_sync(0xffffffffu, v, o);
            if (l2 == 0) s_s[wh] = s_s[wh] * sc_s[wh] + v;
        }
        {
            float sc = sc_s[hh2];
            accLo *= sc; accHi *= sc;
            const float* pp = &pT[hh2 * 68];
#pragma unroll 4
            for (int e = 0; e < cnt; e++) {
                float p = pp[e];
                accLo = fmaf(p, hE_s[e * PADR + j1], accLo);
                accHi = fmaf(p, hE_s[e * PADR + j1 + 32], accHi);
            }
        }
        __syncthreads();
    }
    float inv = (end > beg) ? (1.0f / s_s[hh2]) : 0.f;
    g_agg[(size_t)n * 512 + hh2 * 128 + j1]      = accLo * inv;
    g_agg[(size_t)n * 512 + hh2 * 128 + j1 + 32] = accHi * inv;
}

extern "C" void kernel_launch(void* const* d_in, const int* in_sizes, int n_in,
                              void* d_out, int out_size) {
    const float* hV = (const float*)d_in[0];
    const float* hE = (const float*)d_in[1];
    const int* center = (const int*)d_in[2];
    const float* WQ = (const float*)d_in[5];
    const float* WK = (const float*)d_in[6];
    const float* WV = (const float*)d_in[7];
    const float* WO = (const float*)d_in[8];
    float* out = (float*)d_out;
    int N = in_sizes[0] / 128;
    int E = in_sizes[1] / 128;
    int tiles = (N + 127) / 128;

    cudaFuncSetAttribute(k_gemm_qk, cudaFuncAttributeMaxDynamicSharedMemorySize, SMEM_GEMM);
    cudaFuncSetAttribute(k_gemm_out, cudaFuncAttributeMaxDynamicSharedMemorySize, SMEM_GEMM);

    k_init_rs<<<(N + 256) / 256, 256>>>(N, E);
    k_bounds<<<(E + 255) / 256, 256>>>(center, E);
    k_m1<<<128, 512>>>(WQ, WK);
    k_m2<<<128, 512>>>(WO, WV);
    k_gemm_qk<<<tiles, 512, SMEM_GEMM>>>(hV, N);    // qk = hV @ M1 (HMMA bf16 3-pass)
    k_node<<<N, 256>>>(hE, N);                      // softmax + aggregate
    k_gemm_out<<<tiles, 512, SMEM_GEMM>>>(out, N);  // out = agg @ M2 (HMMA)
}

// round 13
// speedup vs baseline: 1.4985x; 1.0408x over previous
#include <cuda_runtime.h>
#include <cuda_bf16.h>
#include <cstdint>
#include <cstddef>

#define NMAX 50000
#define NEG_BIG (-1.0e30f)

__device__ float g_qk[(size_t)NMAX * 512];   // [n][h*128+j]
__device__ float g_agg[(size_t)NMAX * 512];  // [n][h*128+j]
__device__ int   g_rs[NMAX + 1];
__device__ __nv_bfloat16 g_M1hi[512 * 128], g_M1lo[512 * 128];  // [o][k]
__device__ __nv_bfloat16 g_M2hi[128 * 512], g_M2lo[128 * 512];  // [o][kk]

typedef unsigned long long ull;
__device__ __forceinline__ void f2_fma(ull& a, ull b, ull c) {
    asm("fma.rn.f32x2 %0, %1, %2, %0;" : "+l"(a) : "l"(b), "l"(c));
}
__device__ __forceinline__ float f2_sum(ull v) {
    float x, y; asm("mov.b64 {%0,%1}, %2;" : "=f"(x), "=f"(y) : "l"(v)); return x + y;
}

__device__ __forceinline__ void mma_bf16(float* c, const uint32_t* a, const uint32_t* b) {
    asm volatile(
        "mma.sync.aligned.m16n8k16.row.col.f32.bf16.bf16.f32 "
        "{%0,%1,%2,%3}, {%4,%5,%6,%7}, {%8,%9}, {%0,%1,%2,%3};"
        : "+f"(c[0]), "+f"(c[1]), "+f"(c[2]), "+f"(c[3])
        : "r"(a[0]), "r"(a[1]), "r"(a[2]), "r"(a[3]), "r"(b[0]), "r"(b[1]));
}

// ---- segment bounds ----
__global__ void k_init_rs(int N, int E) {
    int t = blockIdx.x * blockDim.x + threadIdx.x;
    if (t <= N) g_rs[t] = E;
}
__global__ void k_bounds(const int* __restrict__ center, int E) {
    int e = blockIdx.x * blockDim.x + threadIdx.x;
    if (e >= E) return;
    int c = center[e];
    int p = (e == 0) ? -1 : center[e - 1];
    for (int n = p + 1; n <= c; n++) g_rs[n] = e;
}

// ---- combined weights (bf16 hi/lo) ----
__global__ void k_m1(const float* __restrict__ WQ, const float* __restrict__ WK) {
    int k = blockIdx.x, o = threadIdx.x, h = o >> 7, j = o & 127;
    float s = 0.f;
#pragma unroll 8
    for (int d = 0; d < 32; d++)
        s += WQ[(size_t)(h * 32 + d) * 128 + k] * WK[(size_t)(h * 32 + d) * 128 + j];
    s *= 0.17677669529663687f;
    __nv_bfloat16 hi = __float2bfloat16(s);
    g_M1hi[o * 128 + k] = hi;
    g_M1lo[o * 128 + k] = __float2bfloat16(s - __bfloat162float(hi));
}
__global__ void k_m2(const float* __restrict__ WO, const float* __restrict__ WV) {
    int o = blockIdx.x, kk = threadIdx.x, h = kk >> 7, j = kk & 127;
    float s = 0.f;
#pragma unroll 8
    for (int d = 0; d < 32; d++)
        s += WO[(size_t)o * 128 + h * 32 + d] * WV[(size_t)(h * 32 + d) * 128 + j];
    __nv_bfloat16 hi = __float2bfloat16(s);
    g_M2hi[o * 512 + kk] = hi;
    g_M2lo[o * 512 + kk] = __float2bfloat16(s - __bfloat162float(hi));
}

#define PAD 136
#define SMEM_GEMM (4 * 128 * PAD * 2)

__device__ __forceinline__ void store_hl(__nv_bfloat16* Ah, __nv_bfloat16* Al,
                                         int off, float2 v) {
    __nv_bfloat16 hx = __float2bfloat16(v.x), hy = __float2bfloat16(v.y);
    *(__nv_bfloat162*)(Ah + off) = __halves2bfloat162(hx, hy);
    __nv_bfloat16 lx = __float2bfloat16(v.x - __bfloat162float(hx));
    __nv_bfloat16 ly = __float2bfloat16(v.y - __bfloat162float(hy));
    *(__nv_bfloat162*)(Al + off) = __halves2bfloat162(lx, ly);
}

// ---- qk = hV @ M1 ----
__global__ __launch_bounds__(512) void k_gemm_qk(const float* __restrict__ X, int N) {
    extern __shared__ char sm[];
    __nv_bfloat16* Ah = (__nv_bfloat16*)sm;
    __nv_bfloat16* Al = Ah + 128 * PAD;
    __nv_bfloat16* Bh = Al + 128 * PAD;
    __nv_bfloat16* Bl = Bh + 128 * PAD;
    int t = threadIdx.x, lane = t & 31, wid = t >> 5;
    int wr = wid >> 1, wc = wid & 1, g = lane >> 2, tig = lane & 3;
    int n0 = blockIdx.x * 128;

    for (int idx = t; idx < 128 * 64; idx += 512) {
        int r = idx >> 6, kp = (idx & 63) * 2;
        float2 v = (n0 + r < N) ? *(const float2*)(X + (size_t)(n0 + r) * 128 + kp)
                                : make_float2(0.f, 0.f);
        store_hl(Ah, Al, r * PAD + kp, v);
    }
    int ra = 16 * wr + g;
    for (int nc = 0; nc < 4; nc++) {
        if (nc) __syncthreads();
        for (int idx = t; idx < 128 * 16; idx += 512) {
            int r = idx >> 4, k8 = (idx & 15) * 8;
            *(uint4*)(Bh + r * PAD + k8) = *(const uint4*)(g_M1hi + (size_t)(nc * 128 + r) * 128 + k8);
            *(uint4*)(Bl + r * PAD + k8) = *(const uint4*)(g_M1lo + (size_t)(nc * 128 + r) * 128 + k8);
        }
        __syncthreads();
        float acc[8][4];
#pragma unroll
        for (int nt = 0; nt < 8; nt++)
#pragma unroll
            for (int c = 0; c < 4; c++) acc[nt][c] = 0.f;
#pragma unroll
        for (int ks = 0; ks < 8; ks++) {
            int k0 = 16 * ks + tig * 2;
            uint32_t ah[4], al[4];
            ah[0] = *(const uint32_t*)(Ah + ra * PAD + k0);
            ah[1] = *(const uint32_t*)(Ah + (ra + 8) * PAD + k0);
            ah[2] = *(const uint32_t*)(Ah + ra * PAD + k0 + 8);
            ah[3] = *(const uint32_t*)(Ah + (ra + 8) * PAD + k0 + 8);
            al[0] = *(const uint32_t*)(Al + ra * PAD + k0);
            al[1] = *(const uint32_t*)(Al + (ra + 8) * PAD + k0);
            al[2] = *(const uint32_t*)(Al + ra * PAD + k0 + 8);
            al[3] = *(const uint32_t*)(Al + (ra + 8) * PAD + k0 + 8);
#pragma unroll
            for (int nt = 0; nt < 8; nt++) {
                int nb = 64 * wc + 8 * nt + g;
                uint32_t bh[2], bl[2];
                bh[0] = *(const uint32_t*)(Bh + nb * PAD + k0);
                bh[1] = *(const uint32_t*)(Bh + nb * PAD + k0 + 8);
                bl[0] = *(const uint32_t*)(Bl + nb * PAD + k0);
                bl[1] = *(const uint32_t*)(Bl + nb * PAD + k0 + 8);
                mma_bf16(acc[nt], ah, bh);
                mma_bf16(acc[nt], ah, bl);
                mma_bf16(acc[nt], al, bh);
            }
        }
        int r0 = n0 + ra;
#pragma unroll
        for (int nt = 0; nt < 8; nt++) {
            int col = nc * 128 + 64 * wc + 8 * nt + tig * 2;
            if (r0 < N)
                *(float2*)(g_qk + (size_t)r0 * 512 + col) = make_float2(acc[nt][0], acc[nt][1]);
            if (r0 + 8 < N)
                *(float2*)(g_qk + (size_t)(r0 + 8) * 512 + col) = make_float2(acc[nt][2], acc[nt][3]);
        }
    }
}

// ---- out = agg @ M2 ----
__global__ __launch_bounds__(512) void k_gemm_out(float* __restrict__ OUT, int N) {
    extern __shared__ char sm[];
    __nv_bfloat16* Ah = (__nv_bfloat16*)sm;
    __nv_bfloat16* Al = Ah + 128 * PAD;
    __nv_bfloat16* Bh = Al + 128 * PAD;
    __nv_bfloat16* Bl = Bh + 128 * PAD;
    int t = threadIdx.x, lane = t & 31, wid = t >> 5;
    int wr = wid >> 1, wc = wid & 1, g = lane >> 2, tig = lane & 3;
    int n0 = blockIdx.x * 128;
    int ra = 16 * wr + g;

    float acc[8][4];
#pragma unroll
    for (int nt = 0; nt < 8; nt++)
#pragma unroll
        for (int c = 0; c < 4; c++) acc[nt][c] = 0.f;

    for (int kc = 0; kc < 4; kc++) {
        if (kc) __syncthreads();
        for (int idx = t; idx < 128 * 64; idx += 512) {
            int r = idx >> 6, kp = (idx & 63) * 2;
            float2 v = (n0 + r < N)
                ? *(const float2*)(g_agg + (size_t)(n0 + r) * 512 + kc * 128 + kp)
                : make_float2(0.f, 0.f);
            store_hl(Ah, Al, r * PAD + kp, v);
        }
        for (int idx = t; idx < 128 * 16; idx += 512) {
            int r = idx >> 4, k8 = (idx & 15) * 8;
            *(uint4*)(Bh + r * PAD + k8) = *(const uint4*)(g_M2hi + (size_t)r * 512 + kc * 128 + k8);
            *(uint4*)(Bl + r * PAD + k8) = *(const uint4*)(g_M2lo + (size_t)r * 512 + kc * 128 + k8);
        }
        __syncthreads();
#pragma unroll
        for (int ks = 0; ks < 8; ks++) {
            int k0 = 16 * ks + tig * 2;
            uint32_t ah[4], al[4];
            ah[0] = *(const uint32_t*)(Ah + ra * PAD + k0);
            ah[1] = *(const uint32_t*)(Ah + (ra + 8) * PAD + k0);
            ah[2] = *(const uint32_t*)(Ah + ra * PAD + k0 + 8);
            ah[3] = *(const uint32_t*)(Ah + (ra + 8) * PAD + k0 + 8);
            al[0] = *(const uint32_t*)(Al + ra * PAD + k0);
            al[1] = *(const uint32_t*)(Al + (ra + 8) * PAD + k0);
            al[2] = *(const uint32_t*)(Al + ra * PAD + k0 + 8);
            al[3] = *(const uint32_t*)(Al + (ra + 8) * PAD + k0 + 8);
#pragma unroll
            for (int nt = 0; nt < 8; nt++) {
                int nb = 64 * wc + 8 * nt + g;
                uint32_t bh[2], bl[2];
                bh[0] = *(const uint32_t*)(Bh + nb * PAD + k0);
                bh[1] = *(const uint32_t*)(Bh + nb * PAD + k0 + 8);
                bl[0] = *(const uint32_t*)(Bl + nb * PAD + k0);
                bl[1] = *(const uint32_t*)(Bl + nb * PAD + k0 + 8);
                mma_bf16(acc[nt], ah, bh);
                mma_bf16(acc[nt], ah, bl);
                mma_bf16(acc[nt], al, bh);
            }
        }
    }
    int r0 = n0 + ra;
#pragma unroll
    for (int nt = 0; nt < 8; nt++) {
        int col = 64 * wc + 8 * nt + tig * 2;
        if (r0 < N)
            *(float2*)(OUT + (size_t)r0 * 128 + col) = make_float2(acc[nt][0], acc[nt][1]);
        if (r0 + 8 < N)
            *(float2*)(OUT + (size_t)(r0 + 8) * 128 + col) = make_float2(acc[nt][2], acc[nt][3]);
    }
}

// ---- per-node single pass over h_E: SMEM online softmax + aggregation ----
// Fast path for single-chunk nodes (93%): 3 barriers, no online rescale.
#define CH 40
#define PADR 132
__global__ __launch_bounds__(256) void k_node(const float* __restrict__ hE, int N) {
    __shared__ alignas(16) float hE_s[CH * PADR];
    __shared__ alignas(16) float qk_s[4 * PADR];
    __shared__ alignas(16) float lgT[4 * 68];
    __shared__ alignas(16) float pT[4 * 68];
    __shared__ float m_s[4], s_s[4], sc_s[4];
    int t = threadIdx.x;
    int n = blockIdx.x;
    if (n >= N) return;
    int beg = g_rs[n], end = g_rs[n + 1];
    int w = t >> 5, l = t & 31;
    int hh2 = w & 3, jh = w >> 2, j1 = jh * 64 + l;

    if (end - beg <= CH) {
        // ---------- fast path: one chunk, plain softmax ----------
        int cnt = end - beg;
        for (int idx = t; idx < 512; idx += 256) {
            int hh = idx >> 7, j = idx & 127;
            qk_s[hh * PADR + j] = g_qk[(size_t)n * 512 + idx];
        }
        for (int idx = t; idx < cnt * 32; idx += 256) {
            int r = idx >> 5, c4 = idx & 31;
            float4 v = *(const float4*)(hE + (size_t)(beg + r) * 128 + c4 * 4);
            *(float4*)(&hE_s[r * PADR + c4 * 4]) = v;
        }
        __syncthreads();
        {   // logits
            int e = t >> 2, hq = t & 3;
            if (e < cnt) {
                ull acc = 0ull;
                const float* qp = &qk_s[hq * PADR];
                const float* xp = &hE_s[e * PADR];
#pragma unroll
                for (int jj = 0; jj < 32; jj++) {
                    ulonglong2 q4 = *(const ulonglong2*)(qp + jj * 4);
                    ulonglong2 x4 = *(const ulonglong2*)(xp + jj * 4);
                    f2_fma(acc, q4.x, x4.x);
                    f2_fma(acc, q4.y, x4.y);
                }
                lgT[hq * 68 + e] = f2_sum(acc);
            }
        }
        __syncthreads();
        if (w < 4) {  // fused max + exp + sum (head w)
            float v1 = (l < cnt) ? lgT[w * 68 + l] : NEG_BIG;
            float v2 = (l + 32 < cnt) ? lgT[w * 68 + l + 32] : NEG_BIG;
            float mx = fmaxf(v1, v2);
#pragma unroll
            for (int o = 16; o; o >>= 1) mx = fmaxf(mx, __shfl_xor_sync(0xffffffffu, mx, o));
            float p1 = (l < cnt) ? __expf(v1 - mx) : 0.f;
            float p2 = (l + 32 < cnt) ? __expf(v2 - mx) : 0.f;
            pT[w * 68 + l] = p1;
            pT[w * 68 + l + 32] = p2;
            float sv = p1 + p2;
#pragma unroll
            for (int o = 16; o; o >>= 1) sv += __shfl_xor_sync(0xffffffffu, sv, o);
            if (l == 0) s_s[w] = sv;
        }
        __syncthreads();
        {   // accumulate + store
            float aLo = 0.f, aHi = 0.f;
            const float* pp = &pT[hh2 * 68];
#pragma unroll 4
            for (int e = 0; e < cnt; e++) {
                float p = pp[e];
                aLo = fmaf(p, hE_s[e * PADR + j1], aLo);
                aHi = fmaf(p, hE_s[e * PADR + j1 + 32], aHi);
            }
            float inv = (cnt > 0) ? (1.0f / s_s[hh2]) : 0.f;
            g_agg[(size_t)n * 512 + hh2 * 128 + j1]      = aLo * inv;
            g_agg[(size_t)n * 512 + hh2 * 128 + j1 + 32] = aHi * inv;
        }
        return;
    }

    // ---------- general path: online softmax over chunks ----------
    for (int idx = t; idx < 512; idx += 256) {
        int hh = idx >> 7, j = idx & 127;
        qk_s[hh * PADR + j] = g_qk[(size_t)n * 512 + idx];
    }
    if (t < 4) { m_s[t] = NEG_BIG; s_s[t] = 0.f; }
    float accLo = 0.f, accHi = 0.f;
    __syncthreads();

    for (int cs = beg; cs < end; cs += CH) {
        int cnt = min(CH, end - cs);
        for (int idx = t; idx < cnt * 32; idx += 256) {
            int r = idx >> 5, c4 = idx & 31;
            float4 v = *(const float4*)(hE + (size_t)(cs + r) * 128 + c4 * 4);
            *(float4*)(&hE_s[r * PADR + c4 * 4]) = v;
        }
        __syncthreads();
        {
            int e = t >> 2, hq = t & 3;
            float lg = NEG_BIG;
            if (e < cnt) {
                ull acc = 0ull;
                const float* qp = &qk_s[hq * PADR];
                const float* xp = &hE_s[e * PADR];
#pragma unroll
                for (int jj = 0; jj < 32; jj++) {
                    ulonglong2 q4 = *(const ulonglong2*)(qp + jj * 4);
                    ulonglong2 x4 = *(const ulonglong2*)(xp + jj * 4);
                    f2_fma(acc, q4.x, x4.x);
                    f2_fma(acc, q4.y, x4.y);
                }
                lg = f2_sum(acc);
            }
            lgT[hq * 68 + e] = lg;
        }
        __syncthreads();
        if (t < 128) {
            int wh = t >> 5, l2 = t & 31;
            float v = fmaxf(lgT[wh * 68 + l2], lgT[wh * 68 + l2 + 32]);
#pragma unroll
            for (int o = 16; o; o >>= 1) v = fmaxf(v, __shfl_xor_sync(0xffffffffu, v, o));
            if (l2 == 0) {
                float old = m_s[wh], nm = fmaxf(old, v);
                sc_s[wh] = __expf(old - nm);
                m_s[wh] = nm;
            }
        }
        __syncthreads();
        {
            int e = t >> 2, hq = t & 3;
            pT[hq * 68 + e] = (e < cnt) ? __expf(lgT[hq * 68 + e] - m_s[hq]) : 0.f;
        }
        __syncthreads();
        if (t < 128) {
            int wh = t >> 5, l2 = t & 31;
            float v = pT[wh * 68 + l2] + pT[wh * 68 + l2 + 32];
#pragma unroll
            for (int o = 16; o; o >>= 1) v += __shfl_xor_sync(0xffffffffu, v, o);
            if (l2 == 0) s_s[wh] = s_s[wh] * sc_s[wh] + v;
        }
        {
            float sc = sc_s[hh2];
            accLo *= sc; accHi *= sc;
            const float* pp = &pT[hh2 * 68];
#pragma unroll 4
            for (int e = 0; e < cnt; e++) {
                float p = pp[e];
                accLo = fmaf(p, hE_s[e * PADR + j1], accLo);
                accHi = fmaf(p, hE_s[e * PADR + j1 + 32], accHi);
            }
        }
        __syncthreads();
    }
    float inv = (end > beg) ? (1.0f / s_s[hh2]) : 0.f;
    g_agg[(size_t)n * 512 + hh2 * 128 + j1]      = accLo * inv;
    g_agg[(size_t)n * 512 + hh2 * 128 + j1 + 32] = accHi * inv;
}

extern "C" void kernel_launch(void* const* d_in, const int* in_sizes, int n_in,
                              void* d_out, int out_size) {
    const float* hV = (const float*)d_in[0];
    const float* hE = (const float*)d_in[1];
    const int* center = (const int*)d_in[2];
    const float* WQ = (const float*)d_in[5];
    const float* WK = (const float*)d_in[6];
    const float* WV = (const float*)d_in[7];
    const float* WO = (const float*)d_in[8];
    float* out = (float*)d_out;
    int N = in_sizes[0] / 128;
    int E = in_sizes[1] / 128;
    int tiles = (N + 127) / 128;

    cudaFuncSetAttribute(k_gemm_qk, cudaFuncAttributeMaxDynamicSharedMemorySize, SMEM_GEMM);
    cudaFuncSetAttribute(k_gemm_out, cudaFuncAttributeMaxDynamicSharedMemorySize, SMEM_GEMM);

    k_init_rs<<<(N + 256) / 256, 256>>>(N, E);
    k_bounds<<<(E + 255) / 256, 256>>>(center, E);
    k_m1<<<128, 512>>>(WQ, WK);
    k_m2<<<128, 512>>>(WO, WV);
    k_gemm_qk<<<tiles, 512, SMEM_GEMM>>>(hV, N);    // qk = hV @ M1 (HMMA bf16 3-pass)
    k_node<<<N, 256>>>(hE, N);                      // softmax + aggregate
    k_gemm_out<<<tiles, 512, SMEM_GEMM>>>(out, N);  // out = agg @ M2 (HMMA)
}

// round 14
// speedup vs baseline: 1.6110x; 1.0751x over previous
#include <cuda_runtime.h>
#include <cuda_bf16.h>
#include <cstdint>
#include <cstddef>

#define NMAX 50000
#define NEG_BIG (-1.0e30f)

__device__ float g_qk[(size_t)NMAX * 512];   // [n][h*128+j]
__device__ float g_agg[(size_t)NMAX * 512];  // [n][h*128+j]
__device__ int   g_rs[NMAX + 1];
__device__ __nv_bfloat16 g_M1hi[512 * 128], g_M1lo[512 * 128];  // [o][k]
__device__ __nv_bfloat16 g_M2hi[128 * 512], g_M2lo[128 * 512];  // [o][kk]

typedef unsigned long long ull;
__device__ __forceinline__ void f2_fma(ull& a, ull b, ull c) {
    asm("fma.rn.f32x2 %0, %1, %2, %0;" : "+l"(a) : "l"(b), "l"(c));
}
__device__ __forceinline__ float f2_sum(ull v) {
    float x, y; asm("mov.b64 {%0,%1}, %2;" : "=f"(x), "=f"(y) : "l"(v)); return x + y;
}

__device__ __forceinline__ void mma_bf16(float* c, const uint32_t* a, const uint32_t* b) {
    asm volatile(
        "mma.sync.aligned.m16n8k16.row.col.f32.bf16.bf16.f32 "
        "{%0,%1,%2,%3}, {%4,%5,%6,%7}, {%8,%9}, {%0,%1,%2,%3};"
        : "+f"(c[0]), "+f"(c[1]), "+f"(c[2]), "+f"(c[3])
        : "r"(a[0]), "r"(a[1]), "r"(a[2]), "r"(a[3]), "r"(b[0]), "r"(b[1]));
}

// ---- segment bounds ----
__global__ void k_init_rs(int N, int E) {
    int t = blockIdx.x * blockDim.x + threadIdx.x;
    if (t <= N) g_rs[t] = E;
}
__global__ void k_bounds(const int* __restrict__ center, int E) {
    int e = blockIdx.x * blockDim.x + threadIdx.x;
    if (e >= E) return;
    int c = center[e];
    int p = (e == 0) ? -1 : center[e - 1];
    for (int n = p + 1; n <= c; n++) g_rs[n] = e;
}

// ---- combined weights (bf16 hi/lo) ----
__global__ void k_m1(const float* __restrict__ WQ, const float* __restrict__ WK) {
    int k = blockIdx.x, o = threadIdx.x, h = o >> 7, j = o & 127;
    float s = 0.f;
#pragma unroll 8
    for (int d = 0; d < 32; d++)
        s += WQ[(size_t)(h * 32 + d) * 128 + k] * WK[(size_t)(h * 32 + d) * 128 + j];
    s *= 0.17677669529663687f;
    __nv_bfloat16 hi = __float2bfloat16(s);
    g_M1hi[o * 128 + k] = hi;
    g_M1lo[o * 128 + k] = __float2bfloat16(s - __bfloat162float(hi));
}
__global__ void k_m2(const float* __restrict__ WO, const float* __restrict__ WV) {
    int o = blockIdx.x, kk = threadIdx.x, h = kk >> 7, j = kk & 127;
    float s = 0.f;
#pragma unroll 8
    for (int d = 0; d < 32; d++)
        s += WO[(size_t)o * 128 + h * 32 + d] * WV[(size_t)(h * 32 + d) * 128 + j];
    __nv_bfloat16 hi = __float2bfloat16(s);
    g_M2hi[o * 512 + kk] = hi;
    g_M2lo[o * 512 + kk] = __float2bfloat16(s - __bfloat162float(hi));
}

#define PAD 136
// A: 128 rows hi+lo, B: 64 rows hi+lo  => (256+128)*PAD*2 bytes = 104448
#define SMEM_GEMM ((2 * 128 + 2 * 64) * PAD * 2)

__device__ __forceinline__ void store_hl(__nv_bfloat16* Ah, __nv_bfloat16* Al,
                                         int off, float2 v) {
    __nv_bfloat16 hx = __float2bfloat16(v.x), hy = __float2bfloat16(v.y);
    *(__nv_bfloat162*)(Ah + off) = __halves2bfloat162(hx, hy);
    __nv_bfloat16 lx = __float2bfloat16(v.x - __bfloat162float(hx));
    __nv_bfloat16 ly = __float2bfloat16(v.y - __bfloat162float(hy));
    *(__nv_bfloat162*)(Al + off) = __halves2bfloat162(lx, ly);
}

// ---- qk = hV @ M1  (M tile 128, N=512 in 8 chunks of 64, K=128) ----
__global__ __launch_bounds__(512, 2) void k_gemm_qk(const float* __restrict__ X, int N) {
    extern __shared__ char sm[];
    __nv_bfloat16* Ah = (__nv_bfloat16*)sm;
    __nv_bfloat16* Al = Ah + 128 * PAD;
    __nv_bfloat16* Bh = Al + 128 * PAD;
    __nv_bfloat16* Bl = Bh + 64 * PAD;
    int t = threadIdx.x, lane = t & 31, wid = t >> 5;
    int wr = wid >> 1, wc = wid & 1, g = lane >> 2, tig = lane & 3;
    int n0 = blockIdx.x * 128;

    for (int idx = t; idx < 128 * 64; idx += 512) {
        int r = idx >> 6, kp = (idx & 63) * 2;
        float2 v = (n0 + r < N) ? *(const float2*)(X + (size_t)(n0 + r) * 128 + kp)
                                : make_float2(0.f, 0.f);
        store_hl(Ah, Al, r * PAD + kp, v);
    }
    int ra = 16 * wr + g;
    for (int nc = 0; nc < 8; nc++) {
        if (nc) __syncthreads();
        for (int idx = t; idx < 64 * 16; idx += 512) {
            int r = idx >> 4, k8 = (idx & 15) * 8;
            *(uint4*)(Bh + r * PAD + k8) = *(const uint4*)(g_M1hi + (size_t)(nc * 64 + r) * 128 + k8);
            *(uint4*)(Bl + r * PAD + k8) = *(const uint4*)(g_M1lo + (size_t)(nc * 64 + r) * 128 + k8);
        }
        __syncthreads();
        float acc[4][4];
#pragma unroll
        for (int nt = 0; nt < 4; nt++)
#pragma unroll
            for (int c = 0; c < 4; c++) acc[nt][c] = 0.f;
#pragma unroll
        for (int ks = 0; ks < 8; ks++) {
            int k0 = 16 * ks + tig * 2;
            uint32_t ah[4], al[4];
            ah[0] = *(const uint32_t*)(Ah + ra * PAD + k0);
            ah[1] = *(const uint32_t*)(Ah + (ra + 8) * PAD + k0);
            ah[2] = *(const uint32_t*)(Ah + ra * PAD + k0 + 8);
            ah[3] = *(const uint32_t*)(Ah + (ra + 8) * PAD + k0 + 8);
            al[0] = *(const uint32_t*)(Al + ra * PAD + k0);
            al[1] = *(const uint32_t*)(Al + (ra + 8) * PAD + k0);
            al[2] = *(const uint32_t*)(Al + ra * PAD + k0 + 8);
            al[3] = *(const uint32_t*)(Al + (ra + 8) * PAD + k0 + 8);
#pragma unroll
            for (int nt = 0; nt < 4; nt++) {
                int nb = 32 * wc + 8 * nt + g;
                uint32_t bh[2], bl[2];
                bh[0] = *(const uint32_t*)(Bh + nb * PAD + k0);
                bh[1] = *(const uint32_t*)(Bh + nb * PAD + k0 + 8);
                bl[0] = *(const uint32_t*)(Bl + nb * PAD + k0);
                bl[1] = *(const uint32_t*)(Bl + nb * PAD + k0 + 8);
                mma_bf16(acc[nt], ah, bh);
                mma_bf16(acc[nt], ah, bl);
                mma_bf16(acc[nt], al, bh);
            }
        }
        int r0 = n0 + ra;
#pragma unroll
        for (int nt = 0; nt < 4; nt++) {
            int col = nc * 64 + 32 * wc + 8 * nt + tig * 2;
            if (r0 < N)
                *(float2*)(g_qk + (size_t)r0 * 512 + col) = make_float2(acc[nt][0], acc[nt][1]);
            if (r0 + 8 < N)
                *(float2*)(g_qk + (size_t)(r0 + 8) * 512 + col) = make_float2(acc[nt][2], acc[nt][3]);
        }
    }
}

// ---- out = agg @ M2  (M tile 128, N=128, K=512 in 4 chunks; B in 2 sub-chunks) ----
__global__ __launch_bounds__(512, 2) void k_gemm_out(float* __restrict__ OUT, int N) {
    extern __shared__ char sm[];
    __nv_bfloat16* Ah = (__nv_bfloat16*)sm;
    __nv_bfloat16* Al = Ah + 128 * PAD;
    __nv_bfloat16* Bh = Al + 128 * PAD;
    __nv_bfloat16* Bl = Bh + 64 * PAD;
    int t = threadIdx.x, lane = t & 31, wid = t >> 5;
    int wr = wid >> 1, wc = wid & 1, g = lane >> 2, tig = lane & 3;
    int n0 = blockIdx.x * 128;
    int ra = 16 * wr + g;

    float acc[8][4];
#pragma unroll
    for (int a = 0; a < 8; a++)
#pragma unroll
        for (int c = 0; c < 4; c++) acc[a][c] = 0.f;

    for (int kc = 0; kc < 4; kc++) {
        if (kc) __syncthreads();
        for (int idx = t; idx < 128 * 64; idx += 512) {
            int r = idx >> 6, kp = (idx & 63) * 2;
            float2 v = (n0 + r < N)
                ? *(const float2*)(g_agg + (size_t)(n0 + r) * 512 + kc * 128 + kp)
                : make_float2(0.f, 0.f);
            store_hl(Ah, Al, r * PAD + kp, v);
        }
        for (int sub = 0; sub < 2; sub++) {
            if (sub) __syncthreads();
            for (int idx = t; idx < 64 * 16; idx += 512) {
                int r = idx >> 4, k8 = (idx & 15) * 8;
                *(uint4*)(Bh + r * PAD + k8) =
                    *(const uint4*)(g_M2hi + (size_t)(sub * 64 + r) * 512 + kc * 128 + k8);
                *(uint4*)(Bl + r * PAD + k8) =
                    *(const uint4*)(g_M2lo + (size_t)(sub * 64 + r) * 512 + kc * 128 + k8);
            }
            __syncthreads();
#pragma unroll
            for (int ks = 0; ks < 8; ks++) {
                int k0 = 16 * ks + tig * 2;
                uint32_t ah[4], al[4];
                ah[0] = *(const uint32_t*)(Ah + ra * PAD + k0);
                ah[1] = *(const uint32_t*)(Ah + (ra + 8) * PAD + k0);
                ah[2] = *(const uint32_t*)(Ah + ra * PAD + k0 + 8);
                ah[3] = *(const uint32_t*)(Ah + (ra + 8) * PAD + k0 + 8);
                al[0] = *(const uint32_t*)(Al + ra * PAD + k0);
                al[1] = *(const uint32_t*)(Al + (ra + 8) * PAD + k0);
                al[2] = *(const uint32_t*)(Al + ra * PAD + k0 + 8);
                al[3] = *(const uint32_t*)(Al + (ra + 8) * PAD + k0 + 8);
#pragma unroll
                for (int nt = 0; nt < 4; nt++) {
                    int nb = 32 * wc + 8 * nt + g;
                    uint32_t bh[2], bl[2];
                    bh[0] = *(const uint32_t*)(Bh + nb * PAD + k0);
                    bh[1] = *(const uint32_t*)(Bh + nb * PAD + k0 + 8);
                    bl[0] = *(const uint32_t*)(Bl + nb * PAD + k0);
                    bl[1] = *(const uint32_t*)(Bl + nb * PAD + k0 + 8);
                    mma_bf16(acc[sub * 4 + nt], ah, bh);
                    mma_bf16(acc[sub * 4 + nt], ah, bl);
                    mma_bf16(acc[sub * 4 + nt], al, bh);
                }
            }
        }
    }
    int r0 = n0 + ra;
#pragma unroll
    for (int a = 0; a < 8; a++) {
        int col = (a >> 2) * 64 + 32 * wc + 8 * (a & 3) + tig * 2;
        if (r0 < N)
            *(float2*)(OUT + (size_t)r0 * 128 + col) = make_float2(acc[a][0], acc[a][1]);
        if (r0 + 8 < N)
            *(float2*)(OUT + (size_t)(r0 + 8) * 128 + col) = make_float2(acc[a][2], acc[a][3]);
    }
}

// ---- per-node single pass over h_E: SMEM online softmax + aggregation ----
#define CH 40
#define PADR 132
__global__ __launch_bounds__(256) void k_node(const float* __restrict__ hE, int N) {
    __shared__ alignas(16) float hE_s[CH * PADR];
    __shared__ alignas(16) float qk_s[4 * PADR];
    __shared__ alignas(16) float lgT[4 * 68];
    __shared__ alignas(16) float pT[4 * 68];
    __shared__ float m_s[4], s_s[4], sc_s[4];
    int t = threadIdx.x;
    int n = blockIdx.x;
    if (n >= N) return;
    int beg = g_rs[n], end = g_rs[n + 1];
    int w = t >> 5, l = t & 31;
    int hh2 = w & 3, jh = w >> 2, j1 = jh * 64 + l;

    if (end - beg <= CH) {
        // ---------- fast path ----------
        int cnt = end - beg;
        for (int idx = t; idx < 512; idx += 256) {
            int hh = idx >> 7, j = idx & 127;
            qk_s[hh * PADR + j] = g_qk[(size_t)n * 512 + idx];
        }
        for (int idx = t; idx < cnt * 32; idx += 256) {
            int r = idx >> 5, c4 = idx & 31;
            float4 v = *(const float4*)(hE + (size_t)(beg + r) * 128 + c4 * 4);
            *(float4*)(&hE_s[r * PADR + c4 * 4]) = v;
        }
        __syncthreads();
        {
            int e = t >> 2, hq = t & 3;
            if (e < cnt) {
                ull a0 = 0ull, a1 = 0ull;
                const float* qp = &qk_s[hq * PADR];
                const float* xp = &hE_s[e * PADR];
#pragma unroll
                for (int jj = 0; jj < 32; jj++) {
                    ulonglong2 q4 = *(const ulonglong2*)(qp + jj * 4);
                    ulonglong2 x4 = *(const ulonglong2*)(xp + jj * 4);
                    f2_fma(a0, q4.x, x4.x);
                    f2_fma(a1, q4.y, x4.y);
                }
                lgT[hq * 68 + e] = f2_sum(a0) + f2_sum(a1);
            }
        }
        __syncthreads();
        if (w < 4) {
            float v1 = (l < cnt) ? lgT[w * 68 + l] : NEG_BIG;
            float v2 = (l + 32 < cnt) ? lgT[w * 68 + l + 32] : NEG_BIG;
            float mx = fmaxf(v1, v2);
#pragma unroll
            for (int o = 16; o; o >>= 1) mx = fmaxf(mx, __shfl_xor_sync(0xffffffffu, mx, o));
            float p1 = (l < cnt) ? __expf(v1 - mx) : 0.f;
            float p2 = (l + 32 < cnt) ? __expf(v2 - mx) : 0.f;
            pT[w * 68 + l] = p1;
            pT[w * 68 + l + 32] = p2;
            float sv = p1 + p2;
#pragma unroll
            for (int o = 16; o; o >>= 1) sv += __shfl_xor_sync(0xffffffffu, sv, o);
            if (l == 0) s_s[w] = sv;
        }
        __syncthreads();
        {
            float aLo = 0.f, aHi = 0.f;
            const float* pp = &pT[hh2 * 68];
#pragma unroll 4
            for (int e = 0; e < cnt; e++) {
                float p = pp[e];
                aLo = fmaf(p, hE_s[e * PADR + j1], aLo);
                aHi = fmaf(p, hE_s[e * PADR + j1 + 32], aHi);
            }
            float inv = (cnt > 0) ? (1.0f / s_s[hh2]) : 0.f;
            g_agg[(size_t)n * 512 + hh2 * 128 + j1]      = aLo * inv;
            g_agg[(size_t)n * 512 + hh2 * 128 + j1 + 32] = aHi * inv;
        }
        return;
    }

    // ---------- general path ----------
    for (int idx = t; idx < 512; idx += 256) {
        int hh = idx >> 7, j = idx & 127;
        qk_s[hh * PADR + j] = g_qk[(size_t)n * 512 + idx];
    }
    if (t < 4) { m_s[t] = NEG_BIG; s_s[t] = 0.f; }
    float accLo = 0.f, accHi = 0.f;
    __syncthreads();

    for (int cs = beg; cs < end; cs += CH) {
        int cnt = min(CH, end - cs);
        for (int idx = t; idx < cnt * 32; idx += 256) {
            int r = idx >> 5, c4 = idx & 31;
            float4 v = *(const float4*)(hE + (size_t)(cs + r) * 128 + c4 * 4);
            *(float4*)(&hE_s[r * PADR + c4 * 4]) = v;
        }
        __syncthreads();
        {
            int e = t >> 2, hq = t & 3;
            float lg = NEG_BIG;
            if (e < cnt) {
                ull a0 = 0ull, a1 = 0ull;
                const float* qp = &qk_s[hq * PADR];
                const float* xp = &hE_s[e * PADR];
#pragma unroll
                for (int jj = 0; jj < 32; jj++) {
                    ulonglong2 q4 = *(const ulonglong2*)(qp + jj * 4);
                    ulonglong2 x4 = *(const ulonglong2*)(xp + jj * 4);
                    f2_fma(a0, q4.x, x4.x);
                    f2_fma(a1, q4.y, x4.y);
                }
                lg = f2_sum(a0) + f2_sum(a1);
            }
            lgT[hq * 68 + e] = lg;
        }
        __syncthreads();
        if (t < 128) {
            int wh = t >> 5, l2 = t & 31;
            float v = fmaxf(lgT[wh * 68 + l2], lgT[wh * 68 + l2 + 32]);
#pragma unroll
            for (int o = 16; o; o >>= 1) v = fmaxf(v, __shfl_xor_sync(0xffffffffu, v, o));
            if (l2 == 0) {
                float old = m_s[wh], nm = fmaxf(old, v);
                sc_s[wh] = __expf(old - nm);
                m_s[wh] = nm;
            }
        }
        __syncthreads();
        {
            int e = t >> 2, hq = t & 3;
            pT[hq * 68 + e] = (e < cnt) ? __expf(lgT[hq * 68 + e] - m_s[hq]) : 0.f;
        }
        __syncthreads();
        if (t < 128) {
            int wh = t >> 5, l2 = t & 31;
            float v = pT[wh * 68 + l2] + pT[wh * 68 + l2 + 32];
#pragma unroll
            for (int o = 16; o; o >>= 1) v += __shfl_xor_sync(0xffffffffu, v, o);
            if (l2 == 0) s_s[wh] = s_s[wh] * sc_s[wh] + v;
        }
        {
            float sc = sc_s[hh2];
            accLo *= sc; accHi *= sc;
            const float* pp = &pT[hh2 * 68];
#pragma unroll 4
            for (int e = 0; e < cnt; e++) {
                float p = pp[e];
                accLo = fmaf(p, hE_s[e * PADR + j1], accLo);
                accHi = fmaf(p, hE_s[e * PADR + j1 + 32], accHi);
            }
        }
        __syncthreads();
    }
    float inv = (end > beg) ? (1.0f / s_s[hh2]) : 0.f;
    g_agg[(size_t)n * 512 + hh2 * 128 + j1]      = accLo * inv;
    g_agg[(size_t)n * 512 + hh2 * 128 + j1 + 32] = accHi * inv;
}

extern "C" void kernel_launch(void* const* d_in, const int* in_sizes, int n_in,
                              void* d_out, int out_size) {
    const float* hV = (const float*)d_in[0];
    const float* hE = (const float*)d_in[1];
    const int* center = (const int*)d_in[2];
    const float* WQ = (const float*)d_in[5];
    const float* WK = (const float*)d_in[6];
    const float* WV = (const float*)d_in[7];
    const float* WO = (const float*)d_in[8];
    float* out = (float*)d_out;
    int N = in_sizes[0] / 128;
    int E = in_sizes[1] / 128;
    int tiles = (N + 127) / 128;

    cudaFuncSetAttribute(k_gemm_qk, cudaFuncAttributeMaxDynamicSharedMemorySize, SMEM_GEMM);
    cudaFuncSetAttribute(k_gemm_out, cudaFuncAttributeMaxDynamicSharedMemorySize, SMEM_GEMM);

    k_init_rs<<<(N + 256) / 256, 256>>>(N, E);
    k_bounds<<<(E + 255) / 256, 256>>>(center, E);
    k_m1<<<128, 512>>>(WQ, WK);
    k_m2<<<128, 512>>>(WO, WV);
    k_gemm_qk<<<tiles, 512, SMEM_GEMM>>>(hV, N);    // qk = hV @ M1 (HMMA, 2 blocks/SM)
    k_node<<<N, 256>>>(hE, N);                      // softmax + aggregate
    k_gemm_out<<<tiles, 512, SMEM_GEMM>>>(out, N);  // out = agg @ M2 (HMMA, 2 blocks/SM)
}